// round 13
// baseline (speedup 1.0000x reference)
#include <cuda_runtime.h>
#include <cuda_bf16.h>
#include <cstdint>

#define N_SAMP 16384
#define M_CTA  64
#define NCTA   (N_SAMP / M_CTA)   // 256
#define NT     256

// word offsets
#define ZSo  0        // z1 f32 [64][264]
#define AHo  16896    // ACT hi [64][132]
#define ALo  25344    // ACT lo
#define WB0h 33792    // W chunk buf0 hi [256][20]
#define WB0l 38912
#define WB1h 44032    // W chunk buf1 hi
#define WB1l 49152
#define B1o  54272
#define B2o  54528
#define W3o  54784
#define NNo  55040    // [64][4]
#define GDo  55296    // [64][4]
#define SMEM_WORDS 55552
#define SMEM_BYTES (SMEM_WORDS * 4)   // 222208

#define PZ 264
#define PA 132
#define PWA 36    // A-phase W1 tile pitch
#define PW 20     // B/D chunk pitch
#define PE 132    // E-phase W1T pitch
// A-phase/E-phase big tiles live across both chunk buffers:
#define WAh WB0h
#define WAl WB1h
#define WEh WB0h
#define WEl WB1h

__device__ __forceinline__ void mma_bf16(float d[4], const uint32_t a[4],
                                         uint32_t b0, uint32_t b1) {
    asm volatile(
        "mma.sync.aligned.m16n8k16.row.col.f32.bf16.bf16.f32 "
        "{%0,%1,%2,%3}, {%4,%5,%6,%7}, {%8,%9}, {%0,%1,%2,%3};"
        : "+f"(d[0]), "+f"(d[1]), "+f"(d[2]), "+f"(d[3])
        : "r"(a[0]), "r"(a[1]), "r"(a[2]), "r"(a[3]), "r"(b0), "r"(b1));
}

__device__ __forceinline__ void cvt_pair(float x0, float x1, uint32_t& hp, uint32_t& lp) {
    __nv_bfloat16 h0 = __float2bfloat16_rn(x0);
    __nv_bfloat16 h1 = __float2bfloat16_rn(x1);
    float l0 = x0 - __bfloat162float(h0);
    float l1 = x1 - __bfloat162float(h1);
    __nv_bfloat162 hv(h0, h1), lv(__float2bfloat16_rn(l0), __float2bfloat16_rn(l1));
    hp = *reinterpret_cast<uint32_t*>(&hv);
    lp = *reinterpret_cast<uint32_t*>(&lv);
}

__global__ void __launch_bounds__(NT, 1)
learnerct_mma(const float* __restrict__ S, const float* __restrict__ Sdot,
              const float* __restrict__ W1, const float* __restrict__ b1,
              const float* __restrict__ W2, const float* __restrict__ b2,
              const float* __restrict__ W3, float* __restrict__ out)
{
    extern __shared__ uint32_t sw[];
    float* sf = reinterpret_cast<float*>(sw);
    const int tid = threadIdx.x, lane = tid & 31, wid = tid >> 5;
    const int t4 = lane >> 2, q = lane & 3;
    const int mg = wid & 1;        // m-group
    const int nq = wid >> 1;       // n-quarter
    const int m0 = blockIdx.x * M_CTA;

    // ---- stage S -> ACT kp 0..31 ----
    #pragma unroll
    for (int it = 0; it < 8; it++) {
        int fp = it * NT + tid, r = fp >> 5, kp = fp & 31;
        float2 x = *reinterpret_cast<const float2*>(&S[(m0 + r) * 64 + 2 * kp]);
        uint32_t hp, lp; cvt_pair(x.x, x.y, hp, lp);
        sw[AHo + r * PA + kp] = hp;
        sw[ALo + r * PA + kp] = lp;
    }
    // ---- stage W1 [256][32kp] pitch 36 ----
    #pragma unroll
    for (int it = 0; it < 32; it++) {
        int fp = it * NT + tid, n = fp >> 5, kp = fp & 31;
        float2 x = *reinterpret_cast<const float2*>(&W1[n * 64 + 2 * kp]);
        uint32_t hp, lp; cvt_pair(x.x, x.y, hp, lp);
        sw[WAh + n * PWA + kp] = hp;
        sw[WAl + n * PWA + kp] = lp;
    }
    sf[B1o + tid] = b1[tid];
    sf[B2o + tid] = b2[tid];
    sf[W3o + tid] = W3[tid];
    __syncthreads();

    float dacc[2][8][4];
    uint32_t ahi[2][4], alo[2][4];

    // ================= Phase A: z1 = S W1^T + b1 (K=64) =================
    #pragma unroll
    for (int mf = 0; mf < 2; mf++)
        #pragma unroll
        for (int nt = 0; nt < 8; nt++)
            #pragma unroll
            for (int j = 0; j < 4; j++) dacc[mf][nt][j] = 0.0f;
    #pragma unroll
    for (int ks = 0; ks < 4; ks++) {
        int kb = ks * 8;
        #pragma unroll
        for (int mf = 0; mf < 2; mf++) {
            int r0 = mg * 32 + mf * 16 + t4;
            ahi[mf][0] = sw[AHo + r0 * PA + kb + q];
            ahi[mf][1] = sw[AHo + (r0 + 8) * PA + kb + q];
            ahi[mf][2] = sw[AHo + r0 * PA + kb + q + 4];
            ahi[mf][3] = sw[AHo + (r0 + 8) * PA + kb + q + 4];
            alo[mf][0] = sw[ALo + r0 * PA + kb + q];
            alo[mf][1] = sw[ALo + (r0 + 8) * PA + kb + q];
            alo[mf][2] = sw[ALo + r0 * PA + kb + q + 4];
            alo[mf][3] = sw[ALo + (r0 + 8) * PA + kb + q + 4];
        }
        #pragma unroll
        for (int nt = 0; nt < 8; nt++) {
            int nrow = nq * 64 + nt * 8 + t4;
            uint32_t bh0 = sw[WAh + nrow * PWA + kb + q], bh1 = sw[WAh + nrow * PWA + kb + q + 4];
            uint32_t bl0 = sw[WAl + nrow * PWA + kb + q], bl1 = sw[WAl + nrow * PWA + kb + q + 4];
            #pragma unroll
            for (int mf = 0; mf < 2; mf++) {
                mma_bf16(dacc[mf][nt], ahi[mf], bh0, bh1);
                mma_bf16(dacc[mf][nt], ahi[mf], bl0, bl1);
                mma_bf16(dacc[mf][nt], alo[mf], bh0, bh1);
            }
        }
    }
    __syncthreads();   // S reads done before y1 overwrites ACT
    // ep-A: z1 -> ZS, y1 -> ACT
    #pragma unroll
    for (int mf = 0; mf < 2; mf++)
        #pragma unroll
        for (int nt = 0; nt < 8; nt++) {
            int c0 = nq * 64 + nt * 8 + 2 * q, cp = nq * 32 + nt * 4 + q;
            int r0 = mg * 32 + mf * 16 + t4;
            float z0 = dacc[mf][nt][0] + sf[B1o + c0], z1 = dacc[mf][nt][1] + sf[B1o + c0 + 1];
            float z2 = dacc[mf][nt][2] + sf[B1o + c0], z3 = dacc[mf][nt][3] + sf[B1o + c0 + 1];
            *reinterpret_cast<float2*>(&sf[ZSo + r0 * PZ + c0])       = make_float2(z0, z1);
            *reinterpret_cast<float2*>(&sf[ZSo + (r0 + 8) * PZ + c0]) = make_float2(z2, z3);
            uint32_t hp, lp;
            cvt_pair(z0 * z0, z1 * z1, hp, lp);
            sw[AHo + r0 * PA + cp] = hp; sw[ALo + r0 * PA + cp] = lp;
            cvt_pair(z2 * z2, z3 * z3, hp, lp);
            sw[AHo + (r0 + 8) * PA + cp] = hp; sw[ALo + (r0 + 8) * PA + cp] = lp;
        }
    __syncthreads();   // ACT(y1) + ZS visible; W1 tile reads done (buffers reused)

    float2 pf[16];

    // ================= Phase B: z2 = y1 W2^T + b2 : 8 chunks of 32K, dbl-buffered =================
    #pragma unroll
    for (int mf = 0; mf < 2; mf++)
        #pragma unroll
        for (int nt = 0; nt < 8; nt++)
            #pragma unroll
            for (int j = 0; j < 4; j++) dacc[mf][nt][j] = 0.0f;
    // stage chunk 0 -> buf0
    #pragma unroll
    for (int it = 0; it < 16; it++) {
        int combo = it * 8 + wid;
        int n = (combo & 31) * 8 + t4, kp2 = (combo >> 5) * 4 + q;
        float2 x = *reinterpret_cast<const float2*>(&W2[n * 256 + 2 * kp2]);
        uint32_t hp, lp; cvt_pair(x.x, x.y, hp, lp);
        sw[WB0h + n * PW + kp2] = hp;
        sw[WB0l + n * PW + kp2] = lp;
    }
    __syncthreads();
    #pragma unroll 1
    for (int kc = 0; kc < 8; kc++) {
        int bh = (kc & 1) ? WB1h : WB0h, bl = (kc & 1) ? WB1l : WB0l;
        int nh = (kc & 1) ? WB0h : WB1h, nl = (kc & 1) ? WB0l : WB1l;
        if (kc < 7) {
            #pragma unroll
            for (int it = 0; it < 16; it++) {
                int combo = it * 8 + wid;
                int n = (combo & 31) * 8 + t4, kp2 = (combo >> 5) * 4 + q;
                pf[it] = *reinterpret_cast<const float2*>(&W2[n * 256 + (kc + 1) * 32 + 2 * kp2]);
            }
        }
        #pragma unroll
        for (int ks = 0; ks < 2; ks++) {
            int kb = ks * 8, ka = kc * 16 + kb;
            #pragma unroll
            for (int mf = 0; mf < 2; mf++) {
                int r0 = mg * 32 + mf * 16 + t4;
                ahi[mf][0] = sw[AHo + r0 * PA + ka + q];
                ahi[mf][1] = sw[AHo + (r0 + 8) * PA + ka + q];
                ahi[mf][2] = sw[AHo + r0 * PA + ka + q + 4];
                ahi[mf][3] = sw[AHo + (r0 + 8) * PA + ka + q + 4];
                alo[mf][0] = sw[ALo + r0 * PA + ka + q];
                alo[mf][1] = sw[ALo + (r0 + 8) * PA + ka + q];
                alo[mf][2] = sw[ALo + r0 * PA + ka + q + 4];
                alo[mf][3] = sw[ALo + (r0 + 8) * PA + ka + q + 4];
            }
            #pragma unroll
            for (int nt = 0; nt < 8; nt++) {
                int nrow = nq * 64 + nt * 8 + t4;
                uint32_t bh0 = sw[bh + nrow * PW + kb + q], bh1 = sw[bh + nrow * PW + kb + q + 4];
                uint32_t bl0 = sw[bl + nrow * PW + kb + q], bl1 = sw[bl + nrow * PW + kb + q + 4];
                #pragma unroll
                for (int mf = 0; mf < 2; mf++) {
                    mma_bf16(dacc[mf][nt], ahi[mf], bh0, bh1);
                    mma_bf16(dacc[mf][nt], ahi[mf], bl0, bl1);
                    mma_bf16(dacc[mf][nt], alo[mf], bh0, bh1);
                }
            }
        }
        if (kc < 7) {
            #pragma unroll
            for (int it = 0; it < 16; it++) {
                int combo = it * 8 + wid;
                int n = (combo & 31) * 8 + t4, kp2 = (combo >> 5) * 4 + q;
                uint32_t hp, lp; cvt_pair(pf[it].x, pf[it].y, hp, lp);
                sw[nh + n * PW + kp2] = hp;
                sw[nl + n * PW + kp2] = lp;
            }
        }
        __syncthreads();
    }
    // ep-B: u = 2*w3*z2 -> ACT ; nn partials
    {
        float pm[2][2] = {{0.0f, 0.0f}, {0.0f, 0.0f}};
        #pragma unroll
        for (int mf = 0; mf < 2; mf++)
            #pragma unroll
            for (int nt = 0; nt < 8; nt++) {
                int c0 = nq * 64 + nt * 8 + 2 * q, cp = nq * 32 + nt * 4 + q;
                int r0 = mg * 32 + mf * 16 + t4;
                float z0 = dacc[mf][nt][0] + sf[B2o + c0], z1 = dacc[mf][nt][1] + sf[B2o + c0 + 1];
                float z2 = dacc[mf][nt][2] + sf[B2o + c0], z3 = dacc[mf][nt][3] + sf[B2o + c0 + 1];
                float w30 = sf[W3o + c0], w31 = sf[W3o + c0 + 1];
                uint32_t hp, lp;
                cvt_pair(2.0f * w30 * z0, 2.0f * w31 * z1, hp, lp);
                sw[AHo + r0 * PA + cp] = hp; sw[ALo + r0 * PA + cp] = lp;
                cvt_pair(2.0f * w30 * z2, 2.0f * w31 * z3, hp, lp);
                sw[AHo + (r0 + 8) * PA + cp] = hp; sw[ALo + (r0 + 8) * PA + cp] = lp;
                pm[mf][0] = fmaf(w30 * z0, z0, fmaf(w31 * z1, z1, pm[mf][0]));
                pm[mf][1] = fmaf(w30 * z2, z2, fmaf(w31 * z3, z3, pm[mf][1]));
            }
        #pragma unroll
        for (int mf = 0; mf < 2; mf++)
            #pragma unroll
            for (int h = 0; h < 2; h++) {
                pm[mf][h] += __shfl_xor_sync(0xffffffffu, pm[mf][h], 1);
                pm[mf][h] += __shfl_xor_sync(0xffffffffu, pm[mf][h], 2);
            }
        if (q == 0) {
            #pragma unroll
            for (int mf = 0; mf < 2; mf++)
                #pragma unroll
                for (int h = 0; h < 2; h++)
                    sf[NNo + (mg * 32 + mf * 16 + h * 8 + t4) * 4 + nq] = pm[mf][h];
        }
    }

    // ================= Phase D: t = u W2 : 8 chunks (transposed tiles), dbl-buffered =================
    #pragma unroll
    for (int mf = 0; mf < 2; mf++)
        #pragma unroll
        for (int nt = 0; nt < 8; nt++)
            #pragma unroll
            for (int j = 0; j < 4; j++) dacc[mf][nt][j] = 0.0f;
    __syncthreads();   // ep-B ACT writes visible before D MMA reads u
    #pragma unroll
    for (int it = 0; it < 16; it++) {
        int combo = it * 8 + wid;
        int p = (combo & 31) * 8 + t4, hp2 = (combo >> 5) * 4 + q;
        float lo = W2[(2 * hp2) * 256 + p];
        float hi = W2[(2 * hp2 + 1) * 256 + p];
        uint32_t hw, lw; cvt_pair(lo, hi, hw, lw);
        sw[WB0h + p * PW + hp2] = hw;
        sw[WB0l + p * PW + hp2] = lw;
    }
    __syncthreads();
    #pragma unroll 1
    for (int kc = 0; kc < 8; kc++) {
        int bh = (kc & 1) ? WB1h : WB0h, bl = (kc & 1) ? WB1l : WB0l;
        int nh = (kc & 1) ? WB0h : WB1h, nl = (kc & 1) ? WB0l : WB1l;
        if (kc < 7) {
            #pragma unroll
            for (int it = 0; it < 16; it++) {
                int combo = it * 8 + wid;
                int p = (combo & 31) * 8 + t4, hp2 = (combo >> 5) * 4 + q;
                pf[it].x = W2[((kc + 1) * 32 + 2 * hp2) * 256 + p];
                pf[it].y = W2[((kc + 1) * 32 + 2 * hp2 + 1) * 256 + p];
            }
        }
        #pragma unroll
        for (int ks = 0; ks < 2; ks++) {
            int kb = ks * 8, ka = kc * 16 + kb;
            #pragma unroll
            for (int mf = 0; mf < 2; mf++) {
                int r0 = mg * 32 + mf * 16 + t4;
                ahi[mf][0] = sw[AHo + r0 * PA + ka + q];
                ahi[mf][1] = sw[AHo + (r0 + 8) * PA + ka + q];
                ahi[mf][2] = sw[AHo + r0 * PA + ka + q + 4];
                ahi[mf][3] = sw[AHo + (r0 + 8) * PA + ka + q + 4];
                alo[mf][0] = sw[ALo + r0 * PA + ka + q];
                alo[mf][1] = sw[ALo + (r0 + 8) * PA + ka + q];
                alo[mf][2] = sw[ALo + r0 * PA + ka + q + 4];
                alo[mf][3] = sw[ALo + (r0 + 8) * PA + ka + q + 4];
            }
            #pragma unroll
            for (int nt = 0; nt < 8; nt++) {
                int nrow = nq * 64 + nt * 8 + t4;
                uint32_t bh0 = sw[bh + nrow * PW + kb + q], bh1 = sw[bh + nrow * PW + kb + q + 4];
                uint32_t bl0 = sw[bl + nrow * PW + kb + q], bl1 = sw[bl + nrow * PW + kb + q + 4];
                #pragma unroll
                for (int mf = 0; mf < 2; mf++) {
                    mma_bf16(dacc[mf][nt], ahi[mf], bh0, bh1);
                    mma_bf16(dacc[mf][nt], ahi[mf], bl0, bl1);
                    mma_bf16(dacc[mf][nt], alo[mf], bh0, bh1);
                }
            }
        }
        if (kc < 7) {
            #pragma unroll
            for (int it = 0; it < 16; it++) {
                int combo = it * 8 + wid;
                int p = (combo & 31) * 8 + t4, hp2 = (combo >> 5) * 4 + q;
                uint32_t hw, lw; cvt_pair(pf[it].x, pf[it].y, hw, lw);
                sw[nh + p * PW + hp2] = hw;
                sw[nl + p * PW + hp2] = lw;
            }
        }
        __syncthreads();
    }
    // ep-D: v = t * 2*z1 -> ACT ; stage E tile (W1^T) into buffers
    #pragma unroll
    for (int mf = 0; mf < 2; mf++)
        #pragma unroll
        for (int nt = 0; nt < 8; nt++) {
            int c0 = nq * 64 + nt * 8 + 2 * q, cp = nq * 32 + nt * 4 + q;
            int r0 = mg * 32 + mf * 16 + t4;
            float2 za = *reinterpret_cast<float2*>(&sf[ZSo + r0 * PZ + c0]);
            float2 zb = *reinterpret_cast<float2*>(&sf[ZSo + (r0 + 8) * PZ + c0]);
            uint32_t hp, lp;
            cvt_pair(dacc[mf][nt][0] * 2.0f * za.x, dacc[mf][nt][1] * 2.0f * za.y, hp, lp);
            sw[AHo + r0 * PA + cp] = hp; sw[ALo + r0 * PA + cp] = lp;
            cvt_pair(dacc[mf][nt][2] * 2.0f * zb.x, dacc[mf][nt][3] * 2.0f * zb.y, hp, lp);
            sw[AHo + (r0 + 8) * PA + cp] = hp; sw[ALo + (r0 + 8) * PA + cp] = lp;
        }
    #pragma unroll
    for (int it = 0; it < 32; it++) {
        int combo = it * 8 + wid;
        int d = (combo & 7) * 8 + t4, pp = (combo >> 3) * 4 + q;
        float lo = W1[(2 * pp) * 64 + d];
        float hi = W1[(2 * pp + 1) * 64 + d];
        uint32_t hw, lw; cvt_pair(lo, hi, hw, lw);
        sw[WEh + d * PE + pp] = hw;
        sw[WEl + d * PE + pp] = lw;
    }
    __syncthreads();

    // ================= Phase E: grad = v W1 =================
    #pragma unroll
    for (int mf = 0; mf < 2; mf++)
        #pragma unroll
        for (int nt = 0; nt < 2; nt++)
            #pragma unroll
            for (int j = 0; j < 4; j++) dacc[mf][nt][j] = 0.0f;
    #pragma unroll
    for (int ks = 0; ks < 16; ks++) {
        int kb = ks * 8;
        #pragma unroll
        for (int mf = 0; mf < 2; mf++) {
            int r0 = mg * 32 + mf * 16 + t4;
            ahi[mf][0] = sw[AHo + r0 * PA + kb + q];
            ahi[mf][1] = sw[AHo + (r0 + 8) * PA + kb + q];
            ahi[mf][2] = sw[AHo + r0 * PA + kb + q + 4];
            ahi[mf][3] = sw[AHo + (r0 + 8) * PA + kb + q + 4];
            alo[mf][0] = sw[ALo + r0 * PA + kb + q];
            alo[mf][1] = sw[ALo + (r0 + 8) * PA + kb + q];
            alo[mf][2] = sw[ALo + r0 * PA + kb + q + 4];
            alo[mf][3] = sw[ALo + (r0 + 8) * PA + kb + q + 4];
        }
        #pragma unroll
        for (int nt = 0; nt < 2; nt++) {
            int nrow = nq * 16 + nt * 8 + t4;
            uint32_t bh0 = sw[WEh + nrow * PE + kb + q], bh1 = sw[WEh + nrow * PE + kb + q + 4];
            uint32_t bl0 = sw[WEl + nrow * PE + kb + q], bl1 = sw[WEl + nrow * PE + kb + q + 4];
            #pragma unroll
            for (int mf = 0; mf < 2; mf++) {
                mma_bf16(dacc[mf][nt], ahi[mf], bh0, bh1);
                mma_bf16(dacc[mf][nt], ahi[mf], bl0, bl1);
                mma_bf16(dacc[mf][nt], alo[mf], bh0, bh1);
            }
        }
    }
    // ep-E: gd partials
    {
        float gd[2][2] = {{0.0f, 0.0f}, {0.0f, 0.0f}};
        #pragma unroll
        for (int mf = 0; mf < 2; mf++)
            #pragma unroll
            for (int nt = 0; nt < 2; nt++) {
                int cd = nq * 16 + nt * 8 + 2 * q;
                int r0 = mg * 32 + mf * 16 + t4;
                float2 sa = *reinterpret_cast<const float2*>(&Sdot[(m0 + r0) * 64 + cd]);
                float2 sb = *reinterpret_cast<const float2*>(&Sdot[(m0 + r0 + 8) * 64 + cd]);
                gd[mf][0] = fmaf(dacc[mf][nt][0], sa.x, fmaf(dacc[mf][nt][1], sa.y, gd[mf][0]));
                gd[mf][1] = fmaf(dacc[mf][nt][2], sb.x, fmaf(dacc[mf][nt][3], sb.y, gd[mf][1]));
            }
        #pragma unroll
        for (int mf = 0; mf < 2; mf++)
            #pragma unroll
            for (int h = 0; h < 2; h++) {
                gd[mf][h] += __shfl_xor_sync(0xffffffffu, gd[mf][h], 1);
                gd[mf][h] += __shfl_xor_sync(0xffffffffu, gd[mf][h], 2);
            }
        if (q == 0) {
            #pragma unroll
            for (int mf = 0; mf < 2; mf++)
                #pragma unroll
                for (int h = 0; h < 2; h++)
                    sf[GDo + (mg * 32 + mf * 16 + h * 8 + t4) * 4 + nq] = gd[mf][h];
        }
    }
    __syncthreads();

    // ================= Final =================
    {
        int m = tid >> 2, qq = tid & 3;
        float c = 0.0f, sd = 0.0f;
        #pragma unroll
        for (int j = 0; j < 4; j++) {
            float4 s4 = *reinterpret_cast<const float4*>(&S[(m0 + m) * 64 + qq * 16 + 4 * j]);
            float4 t4v = *reinterpret_cast<const float4*>(&Sdot[(m0 + m) * 64 + qq * 16 + 4 * j]);
            c  = fmaf(s4.x, s4.x, fmaf(s4.y, s4.y, fmaf(s4.z, s4.z, fmaf(s4.w, s4.w, c))));
            sd = fmaf(s4.x, t4v.x, fmaf(s4.y, t4v.y, fmaf(s4.z, t4v.z, fmaf(s4.w, t4v.w, sd))));
        }
        c  += __shfl_xor_sync(0xffffffffu, c, 1);  c  += __shfl_xor_sync(0xffffffffu, c, 2);
        sd += __shfl_xor_sync(0xffffffffu, sd, 1); sd += __shfl_xor_sync(0xffffffffu, sd, 2);
        if (qq == 0) {
            float nn = sf[NNo + m * 4] + sf[NNo + m * 4 + 1] + sf[NNo + m * 4 + 2] + sf[NNo + m * 4 + 3];
            float gd = sf[GDo + m * 4] + sf[GDo + m * 4 + 1] + sf[GDo + m * 4 + 2] + sf[GDo + m * 4 + 3];
            out[m0 + m]              = nn * c;
            out[N_SAMP + m0 + m]     = 2.0f * nn * sd + c * gd;
            out[2 * N_SAMP + m0 + m] = c;
        }
    }
}

extern "C" void kernel_launch(void* const* d_in, const int* in_sizes, int n_in,
                              void* d_out, int out_size)
{
    const float* S    = (const float*)d_in[0];
    const float* Sdot = (const float*)d_in[1];
    const float* W1   = (const float*)d_in[2];
    const float* b1   = (const float*)d_in[3];
    const float* W2   = (const float*)d_in[4];
    const float* b2   = (const float*)d_in[5];
    const float* W3   = (const float*)d_in[6];
    float* out = (float*)d_out;

    cudaFuncSetAttribute(learnerct_mma, cudaFuncAttributeMaxDynamicSharedMemorySize, SMEM_BYTES);
    learnerct_mma<<<NCTA, NT, SMEM_BYTES>>>(S, Sdot, W1, b1, W2, b2, W3, out);
}

// round 15
// speedup vs baseline: 1.0253x; 1.0253x over previous
#include <cuda_runtime.h>
#include <cuda_bf16.h>
#include <cstdint>

#define N_SAMP 16384
#define M_CTA  64
#define NCTA   (N_SAMP / M_CTA)   // 256
#define NT     512

// word offsets
#define ZSo 0        // z1 f32 [64][264]
#define AHo 16896    // ACT hi [64][132]
#define ALo 25344    // ACT lo
#define WHo 33792    // W tile hi [256][36] (A/B/D) or [64][132] (E)
#define WLo 43008    // W tile lo
#define B1o 52224
#define B2o 52480
#define W3o 52736
#define NNo 52992    // [64][8]
#define GDo 53504    // [64][8]
#define SMEM_WORDS 54016
#define SMEM_BYTES (SMEM_WORDS * 4)   // 216064

#define PZ 264
#define PA 132
#define PW 36
#define PE 132

__device__ __forceinline__ void mma_bf16(float d[4], const uint32_t a[4],
                                         uint32_t b0, uint32_t b1) {
    asm volatile(
        "mma.sync.aligned.m16n8k16.row.col.f32.bf16.bf16.f32 "
        "{%0,%1,%2,%3}, {%4,%5,%6,%7}, {%8,%9}, {%0,%1,%2,%3};"
        : "+f"(d[0]), "+f"(d[1]), "+f"(d[2]), "+f"(d[3])
        : "r"(a[0]), "r"(a[1]), "r"(a[2]), "r"(a[3]), "r"(b0), "r"(b1));
}

__device__ __forceinline__ void cvt_pair(float x0, float x1, uint32_t& hp, uint32_t& lp) {
    __nv_bfloat16 h0 = __float2bfloat16_rn(x0);
    __nv_bfloat16 h1 = __float2bfloat16_rn(x1);
    float l0 = x0 - __bfloat162float(h0);
    float l1 = x1 - __bfloat162float(h1);
    __nv_bfloat162 hv(h0, h1), lv(__float2bfloat16_rn(l0), __float2bfloat16_rn(l1));
    hp = *reinterpret_cast<uint32_t*>(&hv);
    lp = *reinterpret_cast<uint32_t*>(&lv);
}

__global__ void __launch_bounds__(NT, 1)
learnerct_mma(const float* __restrict__ S, const float* __restrict__ Sdot,
              const float* __restrict__ W1, const float* __restrict__ b1,
              const float* __restrict__ W2, const float* __restrict__ b2,
              const float* __restrict__ W3, float* __restrict__ out)
{
    extern __shared__ uint32_t sw[];
    float* sf = reinterpret_cast<float*>(sw);
    const int tid = threadIdx.x, lane = tid & 31, wid = tid >> 5;   // wid 0..15
    const int t4 = lane >> 2, q = lane & 3;
    const int mg = wid & 1;        // m-group: rows mg*32..+31
    const int ne = wid >> 1;       // n-eighth: cols ne*32..+31
    const int m0 = blockIdx.x * M_CTA;

    // ---- stage S -> ACT kp 0..31 ----
    #pragma unroll
    for (int it = 0; it < 4; it++) {
        int fp = it * NT + tid, r = fp >> 5, kp = fp & 31;
        float2 x = *reinterpret_cast<const float2*>(&S[(m0 + r) * 64 + 2 * kp]);
        uint32_t hp, lp; cvt_pair(x.x, x.y, hp, lp);
        sw[AHo + r * PA + kp] = hp;
        sw[ALo + r * PA + kp] = lp;
    }
    // ---- stage W1 [256][32kp] ----
    #pragma unroll
    for (int it = 0; it < 16; it++) {
        int fp = it * NT + tid, n = fp >> 5, kp = fp & 31;
        float2 x = *reinterpret_cast<const float2*>(&W1[n * 64 + 2 * kp]);
        uint32_t hp, lp; cvt_pair(x.x, x.y, hp, lp);
        sw[WHo + n * PW + kp] = hp;
        sw[WLo + n * PW + kp] = lp;
    }
    if (tid < 256) {
        sf[B1o + tid] = b1[tid];
        sf[B2o + tid] = b2[tid];
        sf[W3o + tid] = W3[tid];
    }
    __syncthreads();

    float dacc[2][4][4];
    uint32_t ahi[2][4], alo[2][4];

    // ================= Phase A: z1 = S W1^T + b1 (K=64) =================
    #pragma unroll
    for (int mf = 0; mf < 2; mf++)
        #pragma unroll
        for (int nt = 0; nt < 4; nt++)
            #pragma unroll
            for (int j = 0; j < 4; j++) dacc[mf][nt][j] = 0.0f;
    #pragma unroll
    for (int ks = 0; ks < 4; ks++) {
        int kb = ks * 8;
        #pragma unroll
        for (int mf = 0; mf < 2; mf++) {
            int r0 = mg * 32 + mf * 16 + t4;
            ahi[mf][0] = sw[AHo + r0 * PA + kb + q];
            ahi[mf][1] = sw[AHo + (r0 + 8) * PA + kb + q];
            ahi[mf][2] = sw[AHo + r0 * PA + kb + q + 4];
            ahi[mf][3] = sw[AHo + (r0 + 8) * PA + kb + q + 4];
            alo[mf][0] = sw[ALo + r0 * PA + kb + q];
            alo[mf][1] = sw[ALo + (r0 + 8) * PA + kb + q];
            alo[mf][2] = sw[ALo + r0 * PA + kb + q + 4];
            alo[mf][3] = sw[ALo + (r0 + 8) * PA + kb + q + 4];
        }
        #pragma unroll
        for (int nt = 0; nt < 4; nt++) {
            int nrow = ne * 32 + nt * 8 + t4;
            uint32_t bh0 = sw[WHo + nrow * PW + kb + q], bh1 = sw[WHo + nrow * PW + kb + q + 4];
            uint32_t bl0 = sw[WLo + nrow * PW + kb + q], bl1 = sw[WLo + nrow * PW + kb + q + 4];
            #pragma unroll
            for (int mf = 0; mf < 2; mf++) {
                mma_bf16(dacc[mf][nt], ahi[mf], bh0, bh1);
                mma_bf16(dacc[mf][nt], ahi[mf], bl0, bl1);
                mma_bf16(dacc[mf][nt], alo[mf], bh0, bh1);
            }
        }
    }
    __syncthreads();   // S reads done before y1 overwrites ACT
    // ep-A: z1 -> ZS, y1 -> ACT
    #pragma unroll
    for (int mf = 0; mf < 2; mf++)
        #pragma unroll
        for (int nt = 0; nt < 4; nt++) {
            int c0 = ne * 32 + nt * 8 + 2 * q, cp = ne * 16 + nt * 4 + q;
            int r0 = mg * 32 + mf * 16 + t4;
            float z0 = dacc[mf][nt][0] + sf[B1o + c0], z1 = dacc[mf][nt][1] + sf[B1o + c0 + 1];
            float z2 = dacc[mf][nt][2] + sf[B1o + c0], z3 = dacc[mf][nt][3] + sf[B1o + c0 + 1];
            *reinterpret_cast<float2*>(&sf[ZSo + r0 * PZ + c0])       = make_float2(z0, z1);
            *reinterpret_cast<float2*>(&sf[ZSo + (r0 + 8) * PZ + c0]) = make_float2(z2, z3);
            uint32_t hp, lp;
            cvt_pair(z0 * z0, z1 * z1, hp, lp);
            sw[AHo + r0 * PA + cp] = hp; sw[ALo + r0 * PA + cp] = lp;
            cvt_pair(z2 * z2, z3 * z3, hp, lp);
            sw[AHo + (r0 + 8) * PA + cp] = hp; sw[ALo + (r0 + 8) * PA + cp] = lp;
        }

    // ================= Phase B: z2 = y1 W2^T + b2 =================
    #pragma unroll
    for (int mf = 0; mf < 2; mf++)
        #pragma unroll
        for (int nt = 0; nt < 4; nt++)
            #pragma unroll
            for (int j = 0; j < 4; j++) dacc[mf][nt][j] = 0.0f;
    for (int kc = 0; kc < 4; kc++) {
        __syncthreads();
        #pragma unroll
        for (int it = 0; it < 16; it++) {
            int fp = it * NT + tid, n = fp >> 5, kp = fp & 31;
            float2 x = *reinterpret_cast<const float2*>(&W2[n * 256 + kc * 64 + 2 * kp]);
            uint32_t hp, lp; cvt_pair(x.x, x.y, hp, lp);
            sw[WHo + n * PW + kp] = hp;
            sw[WLo + n * PW + kp] = lp;
        }
        __syncthreads();
        #pragma unroll
        for (int ks = 0; ks < 4; ks++) {
            int ka = kc * 32 + ks * 8, kb = ks * 8;
            #pragma unroll
            for (int mf = 0; mf < 2; mf++) {
                int r0 = mg * 32 + mf * 16 + t4;
                ahi[mf][0] = sw[AHo + r0 * PA + ka + q];
                ahi[mf][1] = sw[AHo + (r0 + 8) * PA + ka + q];
                ahi[mf][2] = sw[AHo + r0 * PA + ka + q + 4];
                ahi[mf][3] = sw[AHo + (r0 + 8) * PA + ka + q + 4];
                alo[mf][0] = sw[ALo + r0 * PA + ka + q];
                alo[mf][1] = sw[ALo + (r0 + 8) * PA + ka + q];
                alo[mf][2] = sw[ALo + r0 * PA + ka + q + 4];
                alo[mf][3] = sw[ALo + (r0 + 8) * PA + ka + q + 4];
            }
            #pragma unroll
            for (int nt = 0; nt < 4; nt++) {
                int nrow = ne * 32 + nt * 8 + t4;
                uint32_t bh0 = sw[WHo + nrow * PW + kb + q], bh1 = sw[WHo + nrow * PW + kb + q + 4];
                uint32_t bl0 = sw[WLo + nrow * PW + kb + q], bl1 = sw[WLo + nrow * PW + kb + q + 4];
                #pragma unroll
                for (int mf = 0; mf < 2; mf++) {
                    mma_bf16(dacc[mf][nt], ahi[mf], bh0, bh1);
                    mma_bf16(dacc[mf][nt], ahi[mf], bl0, bl1);
                    mma_bf16(dacc[mf][nt], alo[mf], bh0, bh1);
                }
            }
        }
    }
    __syncthreads();   // y1 reads done
    // ep-B: u = 2*w3*z2 -> ACT ; nn partials
    {
        float pm[2][2] = {{0.0f, 0.0f}, {0.0f, 0.0f}};
        #pragma unroll
        for (int mf = 0; mf < 2; mf++)
            #pragma unroll
            for (int nt = 0; nt < 4; nt++) {
                int c0 = ne * 32 + nt * 8 + 2 * q, cp = ne * 16 + nt * 4 + q;
                int r0 = mg * 32 + mf * 16 + t4;
                float z0 = dacc[mf][nt][0] + sf[B2o + c0], z1 = dacc[mf][nt][1] + sf[B2o + c0 + 1];
                float z2 = dacc[mf][nt][2] + sf[B2o + c0], z3 = dacc[mf][nt][3] + sf[B2o + c0 + 1];
                float w30 = sf[W3o + c0], w31 = sf[W3o + c0 + 1];
                uint32_t hp, lp;
                cvt_pair(2.0f * w30 * z0, 2.0f * w31 * z1, hp, lp);
                sw[AHo + r0 * PA + cp] = hp; sw[ALo + r0 * PA + cp] = lp;
                cvt_pair(2.0f * w30 * z2, 2.0f * w31 * z3, hp, lp);
                sw[AHo + (r0 + 8) * PA + cp] = hp; sw[ALo + (r0 + 8) * PA + cp] = lp;
                pm[mf][0] = fmaf(w30 * z0, z0, fmaf(w31 * z1, z1, pm[mf][0]));
                pm[mf][1] = fmaf(w30 * z2, z2, fmaf(w31 * z3, z3, pm[mf][1]));
            }
        #pragma unroll
        for (int mf = 0; mf < 2; mf++)
            #pragma unroll
            for (int h = 0; h < 2; h++) {
                pm[mf][h] += __shfl_xor_sync(0xffffffffu, pm[mf][h], 1);
                pm[mf][h] += __shfl_xor_sync(0xffffffffu, pm[mf][h], 2);
            }
        if (q == 0) {
            #pragma unroll
            for (int mf = 0; mf < 2; mf++)
                #pragma unroll
                for (int h = 0; h < 2; h++)
                    sf[NNo + (mg * 32 + mf * 16 + h * 8 + t4) * 8 + ne] = pm[mf][h];
        }
    }

    // ================= Phase D: t = u W2 (transposed staging) =================
    #pragma unroll
    for (int mf = 0; mf < 2; mf++)
        #pragma unroll
        for (int nt = 0; nt < 4; nt++)
            #pragma unroll
            for (int j = 0; j < 4; j++) dacc[mf][nt][j] = 0.0f;
    for (int kc = 0; kc < 4; kc++) {
        __syncthreads();
        #pragma unroll
        for (int it = 0; it < 16; it++) {
            int combo = it * 16 + wid;
            int p = (combo & 31) * 8 + t4, hp2 = (combo >> 5) * 4 + q;
            float lo = W2[(kc * 64 + 2 * hp2) * 256 + p];
            float hi = W2[(kc * 64 + 2 * hp2 + 1) * 256 + p];
            uint32_t hw, lw; cvt_pair(lo, hi, hw, lw);
            sw[WHo + p * PW + hp2] = hw;
            sw[WLo + p * PW + hp2] = lw;
        }
        __syncthreads();
        #pragma unroll
        for (int ks = 0; ks < 4; ks++) {
            int ka = kc * 32 + ks * 8, kb = ks * 8;
            #pragma unroll
            for (int mf = 0; mf < 2; mf++) {
                int r0 = mg * 32 + mf * 16 + t4;
                ahi[mf][0] = sw[AHo + r0 * PA + ka + q];
                ahi[mf][1] = sw[AHo + (r0 + 8) * PA + ka + q];
                ahi[mf][2] = sw[AHo + r0 * PA + ka + q + 4];
                ahi[mf][3] = sw[AHo + (r0 + 8) * PA + ka + q + 4];
                alo[mf][0] = sw[ALo + r0 * PA + ka + q];
                alo[mf][1] = sw[ALo + (r0 + 8) * PA + ka + q];
                alo[mf][2] = sw[ALo + r0 * PA + ka + q + 4];
                alo[mf][3] = sw[ALo + (r0 + 8) * PA + ka + q + 4];
            }
            #pragma unroll
            for (int nt = 0; nt < 4; nt++) {
                int nrow = ne * 32 + nt * 8 + t4;
                uint32_t bh0 = sw[WHo + nrow * PW + kb + q], bh1 = sw[WHo + nrow * PW + kb + q + 4];
                uint32_t bl0 = sw[WLo + nrow * PW + kb + q], bl1 = sw[WLo + nrow * PW + kb + q + 4];
                #pragma unroll
                for (int mf = 0; mf < 2; mf++) {
                    mma_bf16(dacc[mf][nt], ahi[mf], bh0, bh1);
                    mma_bf16(dacc[mf][nt], ahi[mf], bl0, bl1);
                    mma_bf16(dacc[mf][nt], alo[mf], bh0, bh1);
                }
            }
        }
    }
    __syncthreads();   // u reads done
    // ep-D: v = t * 2*z1 -> ACT ; stage E tile (W1^T)
    #pragma unroll
    for (int mf = 0; mf < 2; mf++)
        #pragma unroll
        for (int nt = 0; nt < 4; nt++) {
            int c0 = ne * 32 + nt * 8 + 2 * q, cp = ne * 16 + nt * 4 + q;
            int r0 = mg * 32 + mf * 16 + t4;
            float2 za = *reinterpret_cast<float2*>(&sf[ZSo + r0 * PZ + c0]);
            float2 zb = *reinterpret_cast<float2*>(&sf[ZSo + (r0 + 8) * PZ + c0]);
            uint32_t hp, lp;
            cvt_pair(dacc[mf][nt][0] * 2.0f * za.x, dacc[mf][nt][1] * 2.0f * za.y, hp, lp);
            sw[AHo + r0 * PA + cp] = hp; sw[ALo + r0 * PA + cp] = lp;
            cvt_pair(dacc[mf][nt][2] * 2.0f * zb.x, dacc[mf][nt][3] * 2.0f * zb.y, hp, lp);
            sw[AHo + (r0 + 8) * PA + cp] = hp; sw[ALo + (r0 + 8) * PA + cp] = lp;
        }
    #pragma unroll
    for (int it = 0; it < 16; it++) {
        int combo = it * 16 + wid;
        int d = (combo & 7) * 8 + t4, pp = (combo >> 3) * 4 + q;
        float lo = W1[(2 * pp) * 64 + d];
        float hi = W1[(2 * pp + 1) * 64 + d];
        uint32_t hw, lw; cvt_pair(lo, hi, hw, lw);
        sw[WHo + d * PE + pp] = hw;
        sw[WLo + d * PE + pp] = lw;
    }
    __syncthreads();

    // ================= Phase E: grad = v W1 (warp covers 8 d-cols) =================
    #pragma unroll
    for (int mf = 0; mf < 2; mf++)
        #pragma unroll
        for (int j = 0; j < 4; j++) dacc[mf][0][j] = 0.0f;
    #pragma unroll
    for (int ks = 0; ks < 16; ks++) {
        int kb = ks * 8;
        #pragma unroll
        for (int mf = 0; mf < 2; mf++) {
            int r0 = mg * 32 + mf * 16 + t4;
            ahi[mf][0] = sw[AHo + r0 * PA + kb + q];
            ahi[mf][1] = sw[AHo + (r0 + 8) * PA + kb + q];
            ahi[mf][2] = sw[AHo + r0 * PA + kb + q + 4];
            ahi[mf][3] = sw[AHo + (r0 + 8) * PA + kb + q + 4];
            alo[mf][0] = sw[ALo + r0 * PA + kb + q];
            alo[mf][1] = sw[ALo + (r0 + 8) * PA + kb + q];
            alo[mf][2] = sw[ALo + r0 * PA + kb + q + 4];
            alo[mf][3] = sw[ALo + (r0 + 8) * PA + kb + q + 4];
        }
        {
            int nrow = ne * 8 + t4;
            uint32_t bh0 = sw[WHo + nrow * PE + kb + q], bh1 = sw[WHo + nrow * PE + kb + q + 4];
            uint32_t bl0 = sw[WLo + nrow * PE + kb + q], bl1 = sw[WLo + nrow * PE + kb + q + 4];
            #pragma unroll
            for (int mf = 0; mf < 2; mf++) {
                mma_bf16(dacc[mf][0], ahi[mf], bh0, bh1);
                mma_bf16(dacc[mf][0], ahi[mf], bl0, bl1);
                mma_bf16(dacc[mf][0], alo[mf], bh0, bh1);
            }
        }
    }
    // ep-E: gd partials
    {
        float gd[2][2] = {{0.0f, 0.0f}, {0.0f, 0.0f}};
        #pragma unroll
        for (int mf = 0; mf < 2; mf++) {
            int cd = ne * 8 + 2 * q;
            int r0 = mg * 32 + mf * 16 + t4;
            float2 sa = *reinterpret_cast<const float2*>(&Sdot[(m0 + r0) * 64 + cd]);
            float2 sb = *reinterpret_cast<const float2*>(&Sdot[(m0 + r0 + 8) * 64 + cd]);
            gd[mf][0] = fmaf(dacc[mf][0][0], sa.x, fmaf(dacc[mf][0][1], sa.y, gd[mf][0]));
            gd[mf][1] = fmaf(dacc[mf][0][2], sb.x, fmaf(dacc[mf][0][3], sb.y, gd[mf][1]));
        }
        #pragma unroll
        for (int mf = 0; mf < 2; mf++)
            #pragma unroll
            for (int h = 0; h < 2; h++) {
                gd[mf][h] += __shfl_xor_sync(0xffffffffu, gd[mf][h], 1);
                gd[mf][h] += __shfl_xor_sync(0xffffffffu, gd[mf][h], 2);
            }
        if (q == 0) {
            #pragma unroll
            for (int mf = 0; mf < 2; mf++)
                #pragma unroll
                for (int h = 0; h < 2; h++)
                    sf[GDo + (mg * 32 + mf * 16 + h * 8 + t4) * 8 + ne] = gd[mf][h];
        }
    }
    __syncthreads();

    // ================= Final =================
    {
        int m = tid >> 3, qq = tid & 7;    // 8 threads per sample, 8 d each
        float c = 0.0f, sd = 0.0f;
        #pragma unroll
        for (int j = 0; j < 2; j++) {
            float4 s4 = *reinterpret_cast<const float4*>(&S[(m0 + m) * 64 + qq * 8 + 4 * j]);
            float4 t4v = *reinterpret_cast<const float4*>(&Sdot[(m0 + m) * 64 + qq * 8 + 4 * j]);
            c  = fmaf(s4.x, s4.x, fmaf(s4.y, s4.y, fmaf(s4.z, s4.z, fmaf(s4.w, s4.w, c))));
            sd = fmaf(s4.x, t4v.x, fmaf(s4.y, t4v.y, fmaf(s4.z, t4v.z, fmaf(s4.w, t4v.w, sd))));
        }
        #pragma unroll
        for (int off = 4; off > 0; off >>= 1) {
            c  += __shfl_xor_sync(0xffffffffu, c,  off);
            sd += __shfl_xor_sync(0xffffffffu, sd, off);
        }
        if (qq == 0) {
            float nn = 0.0f, gd = 0.0f;
            #pragma unroll
            for (int w = 0; w < 8; w++) {
                nn += sf[NNo + m * 8 + w];
                gd += sf[GDo + m * 8 + w];
            }
            out[m0 + m]              = nn * c;
            out[N_SAMP + m0 + m]     = 2.0f * nn * sd + c * gd;
            out[2 * N_SAMP + m0 + m] = c;
        }
    }
}

extern "C" void kernel_launch(void* const* d_in, const int* in_sizes, int n_in,
                              void* d_out, int out_size)
{
    const float* S    = (const float*)d_in[0];
    const float* Sdot = (const float*)d_in[1];
    const float* W1   = (const float*)d_in[2];
    const float* b1   = (const float*)d_in[3];
    const float* W2   = (const float*)d_in[4];
    const float* b2   = (const float*)d_in[5];
    const float* W3   = (const float*)d_in[6];
    float* out = (float*)d_out;

    cudaFuncSetAttribute(learnerct_mma, cudaFuncAttributeMaxDynamicSharedMemorySize, SMEM_BYTES);
    learnerct_mma<<<NCTA, NT, SMEM_BYTES>>>(S, Sdot, W1, b1, W2, b2, W3, out);
}

// round 16
// speedup vs baseline: 1.0766x; 1.0500x over previous
#include <cuda_runtime.h>
#include <cuda_bf16.h>
#include <cstdint>

#define N_SAMP 16384
#define M_CTA  64
#define NCTA   (N_SAMP / M_CTA)   // 256
#define NT     256

// word offsets (total 28416 words = 113664 B -> 2 blocks/SM)
#define AHo 0        // ACT hi [64][132]
#define ALo 8448     // ACT lo
#define WHo 16896    // W chunk hi [256][20]  (E: [64][68])
#define WLo 22016    // W chunk lo
#define B1o 27136
#define B2o 27392
#define W3o 27648
#define NNo 27904    // [64][4]
#define GDo 28160    // [64][4]
#define SMEM_WORDS 28416
#define SMEM_BYTES (SMEM_WORDS * 4)

#define PA 132
#define PW 20
#define PE 68

__device__ float zsg[N_SAMP * 256];   // z1 scratch (global, L2-resident per CTA)

__device__ __forceinline__ void mma_bf16(float d[4], const uint32_t a[4],
                                         uint32_t b0, uint32_t b1) {
    asm volatile(
        "mma.sync.aligned.m16n8k16.row.col.f32.bf16.bf16.f32 "
        "{%0,%1,%2,%3}, {%4,%5,%6,%7}, {%8,%9}, {%0,%1,%2,%3};"
        : "+f"(d[0]), "+f"(d[1]), "+f"(d[2]), "+f"(d[3])
        : "r"(a[0]), "r"(a[1]), "r"(a[2]), "r"(a[3]), "r"(b0), "r"(b1));
}

__device__ __forceinline__ void cvt_pair(float x0, float x1, uint32_t& hp, uint32_t& lp) {
    __nv_bfloat16 h0 = __float2bfloat16_rn(x0);
    __nv_bfloat16 h1 = __float2bfloat16_rn(x1);
    float l0 = x0 - __bfloat162float(h0);
    float l1 = x1 - __bfloat162float(h1);
    __nv_bfloat162 hv(h0, h1), lv(__float2bfloat16_rn(l0), __float2bfloat16_rn(l1));
    hp = *reinterpret_cast<uint32_t*>(&hv);
    lp = *reinterpret_cast<uint32_t*>(&lv);
}

__global__ void __launch_bounds__(NT, 2)
learnerct_mma(const float* __restrict__ S, const float* __restrict__ Sdot,
              const float* __restrict__ W1, const float* __restrict__ b1,
              const float* __restrict__ W2, const float* __restrict__ b2,
              const float* __restrict__ W3, float* __restrict__ out)
{
    extern __shared__ uint32_t sw[];
    float* sf = reinterpret_cast<float*>(sw);
    const int tid = threadIdx.x, lane = tid & 31, wid = tid >> 5;   // wid 0..7
    const int t4 = lane >> 2, q = lane & 3;
    const int mg = wid & 1;        // m-group: rows mg*32..+31
    const int nq = wid >> 1;       // n-quarter: cols nq*64..+63
    const int m0 = blockIdx.x * M_CTA;

    // ---- stage S -> ACT kp 0..31 ----
    #pragma unroll
    for (int it = 0; it < 8; it++) {
        int fp = it * NT + tid, r = fp >> 5, kp = fp & 31;
        float2 x = *reinterpret_cast<const float2*>(&S[(m0 + r) * 64 + 2 * kp]);
        uint32_t hp, lp; cvt_pair(x.x, x.y, hp, lp);
        sw[AHo + r * PA + kp] = hp;
        sw[ALo + r * PA + kp] = lp;
    }
    if (tid < 256) {
        sf[B1o + tid] = b1[tid];
        sf[B2o + tid] = b2[tid];
        sf[W3o + tid] = W3[tid];
    }

    float dacc[2][8][4];
    uint32_t ahi[2][4], alo[2][4];

    // ================= Phase A: z1 = S W1^T + b1 (K=64, 2 chunks) =================
    #pragma unroll
    for (int mf = 0; mf < 2; mf++)
        #pragma unroll
        for (int nt = 0; nt < 8; nt++)
            #pragma unroll
            for (int j = 0; j < 4; j++) dacc[mf][nt][j] = 0.0f;
    for (int kc = 0; kc < 2; kc++) {
        __syncthreads();
        #pragma unroll
        for (int it = 0; it < 16; it++) {
            int fp = it * NT + tid, n = fp >> 4, kp = fp & 15;
            float2 x = *reinterpret_cast<const float2*>(&W1[n * 64 + kc * 32 + 2 * kp]);
            uint32_t hp, lp; cvt_pair(x.x, x.y, hp, lp);
            sw[WHo + n * PW + kp] = hp;
            sw[WLo + n * PW + kp] = lp;
        }
        __syncthreads();
        #pragma unroll
        for (int ks = 0; ks < 2; ks++) {
            int ka = kc * 16 + ks * 8, kb = ks * 8;
            #pragma unroll
            for (int mf = 0; mf < 2; mf++) {
                int r0 = mg * 32 + mf * 16 + t4;
                ahi[mf][0] = sw[AHo + r0 * PA + ka + q];
                ahi[mf][1] = sw[AHo + (r0 + 8) * PA + ka + q];
                ahi[mf][2] = sw[AHo + r0 * PA + ka + q + 4];
                ahi[mf][3] = sw[AHo + (r0 + 8) * PA + ka + q + 4];
                alo[mf][0] = sw[ALo + r0 * PA + ka + q];
                alo[mf][1] = sw[ALo + (r0 + 8) * PA + ka + q];
                alo[mf][2] = sw[ALo + r0 * PA + ka + q + 4];
                alo[mf][3] = sw[ALo + (r0 + 8) * PA + ka + q + 4];
            }
            #pragma unroll
            for (int nt = 0; nt < 8; nt++) {
                int nrow = nq * 64 + nt * 8 + t4;
                uint32_t bh0 = sw[WHo + nrow * PW + kb + q], bh1 = sw[WHo + nrow * PW + kb + q + 4];
                uint32_t bl0 = sw[WLo + nrow * PW + kb + q], bl1 = sw[WLo + nrow * PW + kb + q + 4];
                #pragma unroll
                for (int mf = 0; mf < 2; mf++) {
                    mma_bf16(dacc[mf][nt], ahi[mf], bh0, bh1);
                    mma_bf16(dacc[mf][nt], ahi[mf], bl0, bl1);
                    mma_bf16(dacc[mf][nt], alo[mf], bh0, bh1);
                }
            }
        }
    }
    __syncthreads();   // S reads done before y1 overwrites ACT
    // ep-A: z1 -> global scratch, y1 -> ACT
    #pragma unroll
    for (int mf = 0; mf < 2; mf++)
        #pragma unroll
        for (int nt = 0; nt < 8; nt++) {
            int c0 = nq * 64 + nt * 8 + 2 * q, cp = nq * 32 + nt * 4 + q;
            int r0 = mg * 32 + mf * 16 + t4;
            float z0 = dacc[mf][nt][0] + sf[B1o + c0], z1 = dacc[mf][nt][1] + sf[B1o + c0 + 1];
            float z2 = dacc[mf][nt][2] + sf[B1o + c0], z3 = dacc[mf][nt][3] + sf[B1o + c0 + 1];
            *reinterpret_cast<float2*>(&zsg[(m0 + r0) * 256 + c0])     = make_float2(z0, z1);
            *reinterpret_cast<float2*>(&zsg[(m0 + r0 + 8) * 256 + c0]) = make_float2(z2, z3);
            uint32_t hp, lp;
            cvt_pair(z0 * z0, z1 * z1, hp, lp);
            sw[AHo + r0 * PA + cp] = hp; sw[ALo + r0 * PA + cp] = lp;
            cvt_pair(z2 * z2, z3 * z3, hp, lp);
            sw[AHo + (r0 + 8) * PA + cp] = hp; sw[ALo + (r0 + 8) * PA + cp] = lp;
        }

    // ================= Phase B: z2 = y1 W2^T + b2 (8 chunks of 32-K) =================
    #pragma unroll
    for (int mf = 0; mf < 2; mf++)
        #pragma unroll
        for (int nt = 0; nt < 8; nt++)
            #pragma unroll
            for (int j = 0; j < 4; j++) dacc[mf][nt][j] = 0.0f;
    for (int kc = 0; kc < 8; kc++) {
        __syncthreads();
        #pragma unroll
        for (int it = 0; it < 16; it++) {
            int fp = it * NT + tid, n = fp >> 4, kp = fp & 15;
            float2 x = *reinterpret_cast<const float2*>(&W2[n * 256 + kc * 32 + 2 * kp]);
            uint32_t hp, lp; cvt_pair(x.x, x.y, hp, lp);
            sw[WHo + n * PW + kp] = hp;
            sw[WLo + n * PW + kp] = lp;
        }
        __syncthreads();
        #pragma unroll
        for (int ks = 0; ks < 2; ks++) {
            int ka = kc * 16 + ks * 8, kb = ks * 8;
            #pragma unroll
            for (int mf = 0; mf < 2; mf++) {
                int r0 = mg * 32 + mf * 16 + t4;
                ahi[mf][0] = sw[AHo + r0 * PA + ka + q];
                ahi[mf][1] = sw[AHo + (r0 + 8) * PA + ka + q];
                ahi[mf][2] = sw[AHo + r0 * PA + ka + q + 4];
                ahi[mf][3] = sw[AHo + (r0 + 8) * PA + ka + q + 4];
                alo[mf][0] = sw[ALo + r0 * PA + ka + q];
                alo[mf][1] = sw[ALo + (r0 + 8) * PA + ka + q];
                alo[mf][2] = sw[ALo + r0 * PA + ka + q + 4];
                alo[mf][3] = sw[ALo + (r0 + 8) * PA + ka + q + 4];
            }
            #pragma unroll
            for (int nt = 0; nt < 8; nt++) {
                int nrow = nq * 64 + nt * 8 + t4;
                uint32_t bh0 = sw[WHo + nrow * PW + kb + q], bh1 = sw[WHo + nrow * PW + kb + q + 4];
                uint32_t bl0 = sw[WLo + nrow * PW + kb + q], bl1 = sw[WLo + nrow * PW + kb + q + 4];
                #pragma unroll
                for (int mf = 0; mf < 2; mf++) {
                    mma_bf16(dacc[mf][nt], ahi[mf], bh0, bh1);
                    mma_bf16(dacc[mf][nt], ahi[mf], bl0, bl1);
                    mma_bf16(dacc[mf][nt], alo[mf], bh0, bh1);
                }
            }
        }
    }
    __syncthreads();   // y1 reads done
    // ep-B: u = 2*w3*z2 -> ACT ; nn partials
    {
        float pm[2][2] = {{0.0f, 0.0f}, {0.0f, 0.0f}};
        #pragma unroll
        for (int mf = 0; mf < 2; mf++)
            #pragma unroll
            for (int nt = 0; nt < 8; nt++) {
                int c0 = nq * 64 + nt * 8 + 2 * q, cp = nq * 32 + nt * 4 + q;
                int r0 = mg * 32 + mf * 16 + t4;
                float z0 = dacc[mf][nt][0] + sf[B2o + c0], z1 = dacc[mf][nt][1] + sf[B2o + c0 + 1];
                float z2 = dacc[mf][nt][2] + sf[B2o + c0], z3 = dacc[mf][nt][3] + sf[B2o + c0 + 1];
                float w30 = sf[W3o + c0], w31 = sf[W3o + c0 + 1];
                uint32_t hp, lp;
                cvt_pair(2.0f * w30 * z0, 2.0f * w31 * z1, hp, lp);
                sw[AHo + r0 * PA + cp] = hp; sw[ALo + r0 * PA + cp] = lp;
                cvt_pair(2.0f * w30 * z2, 2.0f * w31 * z3, hp, lp);
                sw[AHo + (r0 + 8) * PA + cp] = hp; sw[ALo + (r0 + 8) * PA + cp] = lp;
                pm[mf][0] = fmaf(w30 * z0, z0, fmaf(w31 * z1, z1, pm[mf][0]));
                pm[mf][1] = fmaf(w30 * z2, z2, fmaf(w31 * z3, z3, pm[mf][1]));
            }
        #pragma unroll
        for (int mf = 0; mf < 2; mf++)
            #pragma unroll
            for (int h = 0; h < 2; h++) {
                pm[mf][h] += __shfl_xor_sync(0xffffffffu, pm[mf][h], 1);
                pm[mf][h] += __shfl_xor_sync(0xffffffffu, pm[mf][h], 2);
            }
        if (q == 0) {
            #pragma unroll
            for (int mf = 0; mf < 2; mf++)
                #pragma unroll
                for (int h = 0; h < 2; h++)
                    sf[NNo + (mg * 32 + mf * 16 + h * 8 + t4) * 4 + nq] = pm[mf][h];
        }
    }

    // ================= Phase D: t = u W2 (8 chunks, transposed staging) =================
    #pragma unroll
    for (int mf = 0; mf < 2; mf++)
        #pragma unroll
        for (int nt = 0; nt < 8; nt++)
            #pragma unroll
            for (int j = 0; j < 4; j++) dacc[mf][nt][j] = 0.0f;
    for (int kc = 0; kc < 8; kc++) {
        __syncthreads();
        #pragma unroll
        for (int it = 0; it < 16; it++) {
            int combo = it * 8 + wid;
            int p = (combo & 31) * 8 + t4, hp2 = (combo >> 5) * 4 + q;
            float lo = W2[(kc * 32 + 2 * hp2) * 256 + p];
            float hi = W2[(kc * 32 + 2 * hp2 + 1) * 256 + p];
            uint32_t hw, lw; cvt_pair(lo, hi, hw, lw);
            sw[WHo + p * PW + hp2] = hw;
            sw[WLo + p * PW + hp2] = lw;
        }
        __syncthreads();
        #pragma unroll
        for (int ks = 0; ks < 2; ks++) {
            int ka = kc * 16 + ks * 8, kb = ks * 8;
            #pragma unroll
            for (int mf = 0; mf < 2; mf++) {
                int r0 = mg * 32 + mf * 16 + t4;
                ahi[mf][0] = sw[AHo + r0 * PA + ka + q];
                ahi[mf][1] = sw[AHo + (r0 + 8) * PA + ka + q];
                ahi[mf][2] = sw[AHo + r0 * PA + ka + q + 4];
                ahi[mf][3] = sw[AHo + (r0 + 8) * PA + ka + q + 4];
                alo[mf][0] = sw[ALo + r0 * PA + ka + q];
                alo[mf][1] = sw[ALo + (r0 + 8) * PA + ka + q];
                alo[mf][2] = sw[ALo + r0 * PA + ka + q + 4];
                alo[mf][3] = sw[ALo + (r0 + 8) * PA + ka + q + 4];
            }
            #pragma unroll
            for (int nt = 0; nt < 8; nt++) {
                int nrow = nq * 64 + nt * 8 + t4;
                uint32_t bh0 = sw[WHo + nrow * PW + kb + q], bh1 = sw[WHo + nrow * PW + kb + q + 4];
                uint32_t bl0 = sw[WLo + nrow * PW + kb + q], bl1 = sw[WLo + nrow * PW + kb + q + 4];
                #pragma unroll
                for (int mf = 0; mf < 2; mf++) {
                    mma_bf16(dacc[mf][nt], ahi[mf], bh0, bh1);
                    mma_bf16(dacc[mf][nt], ahi[mf], bl0, bl1);
                    mma_bf16(dacc[mf][nt], alo[mf], bh0, bh1);
                }
            }
        }
    }
    __syncthreads();   // u reads done
    // ep-D: v = t * 2*z1 (z1 from global scratch) -> ACT
    #pragma unroll
    for (int mf = 0; mf < 2; mf++)
        #pragma unroll
        for (int nt = 0; nt < 8; nt++) {
            int c0 = nq * 64 + nt * 8 + 2 * q, cp = nq * 32 + nt * 4 + q;
            int r0 = mg * 32 + mf * 16 + t4;
            float2 za = *reinterpret_cast<const float2*>(&zsg[(m0 + r0) * 256 + c0]);
            float2 zb = *reinterpret_cast<const float2*>(&zsg[(m0 + r0 + 8) * 256 + c0]);
            uint32_t hp, lp;
            cvt_pair(dacc[mf][nt][0] * 2.0f * za.x, dacc[mf][nt][1] * 2.0f * za.y, hp, lp);
            sw[AHo + r0 * PA + cp] = hp; sw[ALo + r0 * PA + cp] = lp;
            cvt_pair(dacc[mf][nt][2] * 2.0f * zb.x, dacc[mf][nt][3] * 2.0f * zb.y, hp, lp);
            sw[AHo + (r0 + 8) * PA + cp] = hp; sw[ALo + (r0 + 8) * PA + cp] = lp;
        }

    // ================= Phase E: grad = v W1 (2 chunks of W1^T [64][68]) =================
    #pragma unroll
    for (int mf = 0; mf < 2; mf++)
        #pragma unroll
        for (int nt = 0; nt < 2; nt++)
            #pragma unroll
            for (int j = 0; j < 4; j++) dacc[mf][nt][j] = 0.0f;
    for (int ec = 0; ec < 2; ec++) {
        __syncthreads();
        #pragma unroll
        for (int it = 0; it < 16; it++) {
            int combo = it * 8 + wid;
            int d = (combo & 7) * 8 + t4, ppl = (combo >> 3) * 4 + q;
            int pp = ec * 64 + ppl;
            float lo = W1[(2 * pp) * 64 + d];
            float hi = W1[(2 * pp + 1) * 64 + d];
            uint32_t hw, lw; cvt_pair(lo, hi, hw, lw);
            sw[WHo + d * PE + ppl] = hw;
            sw[WLo + d * PE + ppl] = lw;
        }
        __syncthreads();
        #pragma unroll
        for (int ks = 0; ks < 8; ks++) {
            int ka = ec * 64 + ks * 8, kb = ks * 8;
            #pragma unroll
            for (int mf = 0; mf < 2; mf++) {
                int r0 = mg * 32 + mf * 16 + t4;
                ahi[mf][0] = sw[AHo + r0 * PA + ka + q];
                ahi[mf][1] = sw[AHo + (r0 + 8) * PA + ka + q];
                ahi[mf][2] = sw[AHo + r0 * PA + ka + q + 4];
                ahi[mf][3] = sw[AHo + (r0 + 8) * PA + ka + q + 4];
                alo[mf][0] = sw[ALo + r0 * PA + ka + q];
                alo[mf][1] = sw[ALo + (r0 + 8) * PA + ka + q];
                alo[mf][2] = sw[ALo + r0 * PA + ka + q + 4];
                alo[mf][3] = sw[ALo + (r0 + 8) * PA + ka + q + 4];
            }
            #pragma unroll
            for (int nt = 0; nt < 2; nt++) {
                int nrow = nq * 16 + nt * 8 + t4;
                uint32_t bh0 = sw[WHo + nrow * PE + kb + q], bh1 = sw[WHo + nrow * PE + kb + q + 4];
                uint32_t bl0 = sw[WLo + nrow * PE + kb + q], bl1 = sw[WLo + nrow * PE + kb + q + 4];
                #pragma unroll
                for (int mf = 0; mf < 2; mf++) {
                    mma_bf16(dacc[mf][nt], ahi[mf], bh0, bh1);
                    mma_bf16(dacc[mf][nt], ahi[mf], bl0, bl1);
                    mma_bf16(dacc[mf][nt], alo[mf], bh0, bh1);
                }
            }
        }
    }
    // ep-E: gd partials
    {
        float gd[2][2] = {{0.0f, 0.0f}, {0.0f, 0.0f}};
        #pragma unroll
        for (int mf = 0; mf < 2; mf++)
            #pragma unroll
            for (int nt = 0; nt < 2; nt++) {
                int cd = nq * 16 + nt * 8 + 2 * q;
                int r0 = mg * 32 + mf * 16 + t4;
                float2 sa = *reinterpret_cast<const float2*>(&Sdot[(m0 + r0) * 64 + cd]);
                float2 sb = *reinterpret_cast<const float2*>(&Sdot[(m0 + r0 + 8) * 64 + cd]);
                gd[mf][0] = fmaf(dacc[mf][nt][0], sa.x, fmaf(dacc[mf][nt][1], sa.y, gd[mf][0]));
                gd[mf][1] = fmaf(dacc[mf][nt][2], sb.x, fmaf(dacc[mf][nt][3], sb.y, gd[mf][1]));
            }
        #pragma unroll
        for (int mf = 0; mf < 2; mf++)
            #pragma unroll
            for (int h = 0; h < 2; h++) {
                gd[mf][h] += __shfl_xor_sync(0xffffffffu, gd[mf][h], 1);
                gd[mf][h] += __shfl_xor_sync(0xffffffffu, gd[mf][h], 2);
            }
        if (q == 0) {
            #pragma unroll
            for (int mf = 0; mf < 2; mf++)
                #pragma unroll
                for (int h = 0; h < 2; h++)
                    sf[GDo + (mg * 32 + mf * 16 + h * 8 + t4) * 4 + nq] = gd[mf][h];
        }
    }
    __syncthreads();

    // ================= Final =================
    {
        int m = tid >> 2, qq = tid & 3;
        float c = 0.0f, sd = 0.0f;
        #pragma unroll
        for (int j = 0; j < 4; j++) {
            float4 s4 = *reinterpret_cast<const float4*>(&S[(m0 + m) * 64 + qq * 16 + 4 * j]);
            float4 t4v = *reinterpret_cast<const float4*>(&Sdot[(m0 + m) * 64 + qq * 16 + 4 * j]);
            c  = fmaf(s4.x, s4.x, fmaf(s4.y, s4.y, fmaf(s4.z, s4.z, fmaf(s4.w, s4.w, c))));
            sd = fmaf(s4.x, t4v.x, fmaf(s4.y, t4v.y, fmaf(s4.z, t4v.z, fmaf(s4.w, t4v.w, sd))));
        }
        c  += __shfl_xor_sync(0xffffffffu, c, 1);  c  += __shfl_xor_sync(0xffffffffu, c, 2);
        sd += __shfl_xor_sync(0xffffffffu, sd, 1); sd += __shfl_xor_sync(0xffffffffu, sd, 2);
        if (qq == 0) {
            float nn = sf[NNo + m * 4] + sf[NNo + m * 4 + 1] + sf[NNo + m * 4 + 2] + sf[NNo + m * 4 + 3];
            float gd = sf[GDo + m * 4] + sf[GDo + m * 4 + 1] + sf[GDo + m * 4 + 2] + sf[GDo + m * 4 + 3];
            out[m0 + m]              = nn * c;
            out[N_SAMP + m0 + m]     = 2.0f * nn * sd + c * gd;
            out[2 * N_SAMP + m0 + m] = c;
        }
    }
}

extern "C" void kernel_launch(void* const* d_in, const int* in_sizes, int n_in,
                              void* d_out, int out_size)
{
    const float* S    = (const float*)d_in[0];
    const float* Sdot = (const float*)d_in[1];
    const float* W1   = (const float*)d_in[2];
    const float* b1   = (const float*)d_in[3];
    const float* W2   = (const float*)d_in[4];
    const float* b2   = (const float*)d_in[5];
    const float* W3   = (const float*)d_in[6];
    float* out = (float*)d_out;

    cudaFuncSetAttribute(learnerct_mma, cudaFuncAttributeMaxDynamicSharedMemorySize, SMEM_BYTES);
    learnerct_mma<<<NCTA, NT, SMEM_BYTES>>>(S, Sdot, W1, b1, W2, b2, W3, out);
}